// round 4
// baseline (speedup 1.0000x reference)
#include <cuda_runtime.h>

#define BT      4096      // B*T = 2*2048
#define D_MODEL 1024
#define N_HEADS 16
#define HD      64
#define T_SEQ   2048

// ---------------- scratch (no allocations allowed) ----------------
__device__ float g_Q[BT * D_MODEL];     // 16 MB
__device__ float g_KV[BT * 128];        // 2 MB   (K in cols 0..63, V in 64..127)
__device__ float g_Y[BT * D_MODEL];     // 16 MB
__device__ float g_Wkv[D_MODEL * 128];  // 0.5 MB (Wk | Wv packed)

// ---------------- pack Wk|Wv into one N=128 weight ----------------
__global__ void pack_kv_kernel(const float* __restrict__ Wk,
                               const float* __restrict__ Wv) {
    int i = blockIdx.x * blockDim.x + threadIdx.x;
    if (i >= D_MODEL * 128) return;
    int r = i >> 7, c = i & 127;
    g_Wkv[i] = (c < HD) ? Wk[r * HD + c] : Wv[r * HD + (c - HD)];
}

// ---------------- tiled fp32 GEMM: C[M,N] = A[M,K] @ B[K,N] ----------------
// 256 threads, (BM/TM)*(BN/TN) must equal 256. All dims divide tile sizes.
template<int BM, int BN, int BK, int TM, int TN>
__global__ __launch_bounds__(256)
void sgemm_kernel(const float* __restrict__ A, const float* __restrict__ Bm,
                  float* __restrict__ C, int M, int N, int K)
{
    __shared__ float As[BK][BM];   // A stored transposed (k-major)
    __shared__ float Bs[BK][BN];

    const int tid = threadIdx.x;
    const int threadCol = tid % (BN / TN);
    const int threadRow = tid / (BN / TN);
    const int rowBase = blockIdx.y * BM;
    const int colBase = blockIdx.x * BN;

    const int innerRowA = tid / (BK / 4);
    const int innerColA = (tid % (BK / 4)) * 4;
    constexpr int strideA = (256 * 4) / BK;
    const int innerRowB = tid / (BN / 4);
    const int innerColB = (tid % (BN / 4)) * 4;
    constexpr int strideB = (256 * 4) / BN;

    float res[TM * TN];
    #pragma unroll
    for (int i = 0; i < TM * TN; ++i) res[i] = 0.0f;
    float regM[TM], regN[TN];

    for (int bk = 0; bk < K; bk += BK) {
        #pragma unroll
        for (int off = 0; off < BM; off += strideA) {
            float4 t = *(const float4*)&A[(rowBase + innerRowA + off) * K + bk + innerColA];
            As[innerColA + 0][innerRowA + off] = t.x;
            As[innerColA + 1][innerRowA + off] = t.y;
            As[innerColA + 2][innerRowA + off] = t.z;
            As[innerColA + 3][innerRowA + off] = t.w;
        }
        #pragma unroll
        for (int off = 0; off < BK; off += strideB) {
            *(float4*)&Bs[innerRowB + off][innerColB] =
                *(const float4*)&Bm[(bk + innerRowB + off) * N + colBase + innerColB];
        }
        __syncthreads();

        #pragma unroll
        for (int kk = 0; kk < BK; ++kk) {
            #pragma unroll
            for (int i = 0; i < TM; ++i) regM[i] = As[kk][threadRow * TM + i];
            #pragma unroll
            for (int j = 0; j < TN; ++j) regN[j] = Bs[kk][threadCol * TN + j];
            #pragma unroll
            for (int i = 0; i < TM; ++i)
                #pragma unroll
                for (int j = 0; j < TN; ++j)
                    res[i * TN + j] += regM[i] * regN[j];
        }
        __syncthreads();
    }

    #pragma unroll
    for (int i = 0; i < TM; ++i) {
        #pragma unroll
        for (int j = 0; j < TN; j += 4) {
            float4 t;
            t.x = res[i * TN + j + 0];
            t.y = res[i * TN + j + 1];
            t.z = res[i * TN + j + 2];
            t.w = res[i * TN + j + 3];
            *(float4*)&C[(rowBase + threadRow * TM + i) * N + colBase + threadCol * TN + j] = t;
        }
    }
}

// ---------------- causal MQA flash attention ----------------
// Grid: (32 q-tiles, 16 heads, 2 batches). Block: 256 threads = 16x16,
// each thread owns a 4x4 patch of the 64x64 S tile and of the 64x64 O tile.
// K is stored kk-major in smem (so the tx-varying access is cheap); the same
// buffer is reused for P^T in the P@V phase.
__global__ __launch_bounds__(256)
void flash_kernel(const float* __restrict__ Q, const float* __restrict__ KV,
                  float* __restrict__ Y)
{
    extern __shared__ float sm[];
    float* Qs = sm;                 // [64][65]   row-major (r, d)
    float* Kt = sm + 64 * 65;       // [64][65]   (d, c);  reused as P^T (c, r)
    float* Vs = sm + 2 * 64 * 65;   // [64][64]   (c, d)   16B-aligned offset

    const int qt  = blockIdx.x;
    const int h   = blockIdx.y;
    const int b   = blockIdx.z;
    const int tid = threadIdx.x;
    const int ty  = tid >> 4;   // 0..15: query-row group (rows ty*4 .. ty*4+3)
    const int tx  = tid & 15;   // 0..15: col group

    const int rowQ0 = b * T_SEQ + qt * 64;
    const int rowK0 = b * T_SEQ;

    // Load Q tile (pre-scaled by 1/sqrt(64) = 0.125)
    #pragma unroll
    for (int p = 0; p < 4; ++p) {
        int lin = p * 1024 + tid * 4;
        int r = lin >> 6;
        int d = lin & 63;
        float4 v = *(const float4*)&Q[(rowQ0 + r) * D_MODEL + h * HD + d];
        Qs[r * 65 + d + 0] = v.x * 0.125f;
        Qs[r * 65 + d + 1] = v.y * 0.125f;
        Qs[r * 65 + d + 2] = v.z * 0.125f;
        Qs[r * 65 + d + 3] = v.w * 0.125f;
    }

    float acc[16];
    #pragma unroll
    for (int i = 0; i < 16; ++i) acc[i] = 0.0f;
    float mprev[4], lsum[4];
    #pragma unroll
    for (int i = 0; i < 4; ++i) { mprev[i] = -1e30f; lsum[i] = 0.0f; }

    for (int kt = 0; kt <= qt; ++kt) {
        __syncthreads();   // prior iter done reading Kt(P)/Vs; Qs visible on iter 0
        // Load K (transposed to kk-major) and V (natural) for this kv tile
        #pragma unroll
        for (int p = 0; p < 4; ++p) {
            int lin = p * 1024 + tid * 4;
            int c = lin >> 6;
            int d = lin & 63;
            const float* kvrow = &KV[(rowK0 + kt * 64 + c) * 128];
            float4 k4 = *(const float4*)&kvrow[d];
            Kt[(d + 0) * 65 + c] = k4.x;
            Kt[(d + 1) * 65 + c] = k4.y;
            Kt[(d + 2) * 65 + c] = k4.z;
            Kt[(d + 3) * 65 + c] = k4.w;
            *(float4*)&Vs[c * 64 + d] = *(const float4*)&kvrow[64 + d];
        }
        __syncthreads();

        // S = (Q * 1/8) @ K^T  (64x64, 4x4 per thread)
        float s[16];
        #pragma unroll
        for (int i = 0; i < 16; ++i) s[i] = 0.0f;
        #pragma unroll 4
        for (int kk = 0; kk < HD; ++kk) {
            float rq[4], rk[4];
            #pragma unroll
            for (int i = 0; i < 4; ++i) rq[i] = Qs[(ty * 4 + i) * 65 + kk];
            #pragma unroll
            for (int j = 0; j < 4; ++j) rk[j] = Kt[kk * 65 + tx * 4 + j];
            #pragma unroll
            for (int i = 0; i < 4; ++i)
                #pragma unroll
                for (int j = 0; j < 4; ++j)
                    s[i * 4 + j] += rq[i] * rk[j];
        }

        // Causal mask: only the diagonal tile needs masking
        if (kt == qt) {
            #pragma unroll
            for (int i = 0; i < 4; ++i)
                #pragma unroll
                for (int j = 0; j < 4; ++j)
                    if (tx * 4 + j > ty * 4 + i) s[i * 4 + j] = -1e30f;
        }

        // Online softmax: row reductions over the 16 tx lanes (intra-warp shfl)
        #pragma unroll
        for (int i = 0; i < 4; ++i) {
            float mx = fmaxf(fmaxf(s[i*4+0], s[i*4+1]), fmaxf(s[i*4+2], s[i*4+3]));
            #pragma unroll
            for (int o = 8; o >= 1; o >>= 1)
                mx = fmaxf(mx, __shfl_xor_sync(0xffffffffu, mx, o));
            float mnew = fmaxf(mprev[i], mx);
            float sc   = __expf(mprev[i] - mnew);
            float rs = 0.0f;
            #pragma unroll
            for (int j = 0; j < 4; ++j) {
                s[i*4+j] = __expf(s[i*4+j] - mnew);
                rs += s[i*4+j];
            }
            #pragma unroll
            for (int o = 8; o >= 1; o >>= 1)
                rs += __shfl_xor_sync(0xffffffffu, rs, o);
            lsum[i]  = lsum[i] * sc + rs;
            mprev[i] = mnew;
            #pragma unroll
            for (int j = 0; j < 4; ++j) acc[i*4+j] *= sc;
        }

        // Stage P^T into the K buffer (all S reads of Kt are done)
        __syncthreads();
        #pragma unroll
        for (int j = 0; j < 4; ++j)
            #pragma unroll
            for (int i = 0; i < 4; ++i)
                Kt[(tx * 4 + j) * 65 + ty * 4 + i] = s[i * 4 + j];
        __syncthreads();

        // O += P @ V   (thread owns rows ty*4.., dims tx*4..)
        #pragma unroll 4
        for (int c = 0; c < 64; ++c) {
            float rp[4];
            #pragma unroll
            for (int i = 0; i < 4; ++i) rp[i] = Kt[c * 65 + ty * 4 + i];
            float4 v4 = *(const float4*)&Vs[c * 64 + tx * 4];
            #pragma unroll
            for (int i = 0; i < 4; ++i) {
                acc[i*4+0] += rp[i] * v4.x;
                acc[i*4+1] += rp[i] * v4.y;
                acc[i*4+2] += rp[i] * v4.z;
                acc[i*4+3] += rp[i] * v4.w;
            }
        }
    }

    // Normalize and write Y (layout (B,T,h,d) == (BT, 1024) with col = h*64+d)
    #pragma unroll
    for (int i = 0; i < 4; ++i) {
        float inv = 1.0f / lsum[i];
        float4 o;
        o.x = acc[i*4+0] * inv;
        o.y = acc[i*4+1] * inv;
        o.z = acc[i*4+2] * inv;
        o.w = acc[i*4+3] * inv;
        *(float4*)&Y[(rowQ0 + ty * 4 + i) * D_MODEL + h * HD + tx * 4] = o;
    }
}

// ---------------- launch ----------------
extern "C" void kernel_launch(void* const* d_in, const int* in_sizes, int n_in,
                              void* d_out, int out_size) {
    const float* x  = (const float*)d_in[0];
    const float* Wq = (const float*)d_in[1];
    const float* Wk = (const float*)d_in[2];
    const float* Wv = (const float*)d_in[3];
    const float* Wo = (const float*)d_in[4];
    float* out = (float*)d_out;

    float *Qb, *KVb, *Yb, *Wkvb;
    cudaGetSymbolAddress((void**)&Qb,   g_Q);
    cudaGetSymbolAddress((void**)&KVb,  g_KV);
    cudaGetSymbolAddress((void**)&Yb,   g_Y);
    cudaGetSymbolAddress((void**)&Wkvb, g_Wkv);

    const int flash_smem = (2 * 64 * 65 + 64 * 64) * (int)sizeof(float);  // 49664 B
    cudaFuncSetAttribute(flash_kernel,
                         cudaFuncAttributeMaxDynamicSharedMemorySize, flash_smem);

    // 1) pack Wk|Wv
    pack_kv_kernel<<<(D_MODEL * 128 + 255) / 256, 256>>>(Wk, Wv);
    // 2) Q = x @ Wq            (4096 x 1024 x 1024)
    sgemm_kernel<128,128,16,8,8><<<dim3(D_MODEL/128, BT/128), 256>>>(x, Wq, Qb, BT, D_MODEL, D_MODEL);
    // 3) KV = x @ [Wk|Wv]      (4096 x 128 x 1024)
    sgemm_kernel<64,128,16,4,8><<<dim3(1, BT/64), 256>>>(x, Wkvb, KVb, BT, 128, D_MODEL);
    // 4) causal MQA attention  -> Y
    flash_kernel<<<dim3(T_SEQ/64, N_HEADS, 2), 256, flash_smem>>>(Qb, KVb, Yb);
    // 5) out = Y @ Wo          (4096 x 1024 x 1024)
    sgemm_kernel<128,128,16,8,8><<<dim3(D_MODEL/128, BT/128), 256>>>(Yb, Wo, out, BT, D_MODEL, D_MODEL);
}

// round 6
// speedup vs baseline: 1.1810x; 1.1810x over previous
#include <cuda_runtime.h>

typedef unsigned long long u64;

#define BT 4096      // B*T
#define DM 1024
#define NH 16
#define HD 64
#define TS 2048

// ---------------- scratch ----------------
__device__ float g_Q [BT*DM];   // 16 MB  (natural [bt][d])
__device__ float g_Kt[HD*BT];   // 1 MB   (TRANSPOSED: [kk][bt])
__device__ float g_V [BT*HD];   // 1 MB   (natural [bt][kk])
__device__ float g_Y [BT*DM];   // 16 MB

// ---------------- f32x2 packed helpers ----------------
__device__ __forceinline__ void fma2(u64& d, u64 a, u64 b){
    asm("fma.rn.f32x2 %0, %1, %2, %0;" : "+l"(d) : "l"(a), "l"(b));
}
__device__ __forceinline__ u64 dup2(float x){
    u64 r; asm("mov.b64 %0, {%1, %1};" : "=l"(r) : "f"(x)); return r;
}
__device__ __forceinline__ u64 mul2(u64 a, u64 b){
    u64 r; asm("mul.rn.f32x2 %0, %1, %2;" : "=l"(r) : "l"(a), "l"(b)); return r;
}
__device__ __forceinline__ float2 unpk(u64 v){
    float2 f; asm("mov.b64 {%0, %1}, %2;" : "=f"(f.x), "=f"(f.y) : "l"(v)); return f;
}

// ---------------- packed-fp32 GEMM: C[M,N] = A[M,K] @ B[K,N] ----------------
// 256 threads; (BM/TM)*(BN/TN) == 256. TRANS stores C transposed ([N][M]).
template<int BM, int BN, int BK, int TM, int TN, bool TRANS>
__global__ __launch_bounds__(256)
void sgemm2(const float* __restrict__ A, const float* __restrict__ Bm,
            float* __restrict__ C, int M, int N, int K)
{
    __shared__ float As[BK*BM];   // k-major (transposed A tile)
    __shared__ float Bs[BK*BN];

    const int tid = threadIdx.x;
    const int tc  = tid % (BN/TN);
    const int tr  = tid / (BN/TN);
    const int rowBase = blockIdx.y * BM;
    const int colBase = blockIdx.x * BN;

    const int irA = tid / (BK/4);
    const int icA = (tid % (BK/4)) * 4;
    constexpr int sA = (256*4)/BK;
    const int irB = tid / (BN/4);
    const int icB = (tid % (BN/4)) * 4;
    constexpr int sB = (256*4)/BN;

    u64 res2[TM*(TN/2)];
    #pragma unroll
    for (int i = 0; i < TM*(TN/2); ++i) res2[i] = 0ull;

    for (int bk = 0; bk < K; bk += BK) {
        #pragma unroll
        for (int off = 0; off < BM; off += sA) {
            float4 t = *(const float4*)&A[(rowBase+irA+off)*K + bk + icA];
            As[(icA+0)*BM + irA+off] = t.x;
            As[(icA+1)*BM + irA+off] = t.y;
            As[(icA+2)*BM + irA+off] = t.z;
            As[(icA+3)*BM + irA+off] = t.w;
        }
        #pragma unroll
        for (int off = 0; off < BK; off += sB)
            *(float4*)&Bs[(irB+off)*BN + icB] =
                *(const float4*)&Bm[(bk+irB+off)*N + colBase + icB];
        __syncthreads();

        #pragma unroll
        for (int kk = 0; kk < BK; ++kk) {
            float regM[TM];
            u64 regN[TN/2];
            #pragma unroll
            for (int q = 0; q < TM/4; ++q)
                *(float4*)&regM[q*4] = *(const float4*)&As[kk*BM + tr*TM + q*4];
            #pragma unroll
            for (int q = 0; q < TN/4; ++q) {
                ulonglong2 t = *(const ulonglong2*)&Bs[kk*BN + tc*TN + q*4];
                regN[q*2] = t.x; regN[q*2+1] = t.y;
            }
            #pragma unroll
            for (int i = 0; i < TM; ++i) {
                u64 a = dup2(regM[i]);
                #pragma unroll
                for (int j = 0; j < TN/2; ++j)
                    fma2(res2[i*(TN/2)+j], a, regN[j]);
            }
        }
        __syncthreads();
    }

    if (!TRANS) {
        #pragma unroll
        for (int i = 0; i < TM; ++i)
            #pragma unroll
            for (int jq = 0; jq < TN/4; ++jq) {
                float2 a = unpk(res2[i*(TN/2)+jq*2]);
                float2 b = unpk(res2[i*(TN/2)+jq*2+1]);
                float4 o = make_float4(a.x, a.y, b.x, b.y);
                *(float4*)&C[(rowBase+tr*TM+i)*N + colBase+tc*TN+jq*4] = o;
            }
    } else {
        float rs[TM*TN];
        #pragma unroll
        for (int i = 0; i < TM; ++i)
            #pragma unroll
            for (int j = 0; j < TN/2; ++j) {
                float2 a = unpk(res2[i*(TN/2)+j]);
                rs[i*TN + j*2]   = a.x;
                rs[i*TN + j*2+1] = a.y;
            }
        #pragma unroll
        for (int j = 0; j < TN; ++j)
            #pragma unroll
            for (int iq = 0; iq < TM/4; ++iq) {
                float4 o = make_float4(rs[(iq*4+0)*TN+j], rs[(iq*4+1)*TN+j],
                                       rs[(iq*4+2)*TN+j], rs[(iq*4+3)*TN+j]);
                *(float4*)&C[(colBase+tc*TN+j)*M + rowBase+tr*TM+iq*4] = o;
            }
    }
}

// ---------------- causal MQA flash attention (f32x2 packed) ----------------
// Grid: (32 q-tiles, 16 heads, 2 batches). 256 threads = 16x16; each thread
// owns a 4x4 patch of the 64x64 S tile (packed as 8 f32x2) and 4 rows x 4 dims
// of O. Q transposed to kk-major once per block; K arrives pre-transposed.
__global__ __launch_bounds__(256)
void flash2(const float* __restrict__ Q, const float* __restrict__ Kt,
            const float* __restrict__ V, float* __restrict__ Y)
{
    extern __shared__ float smx[];
    float* Qt  = smx;             // [64][68]  kk-major Q (pre-scaled)
    float* KtP = smx + 64*68;     // [64][68]  kk-major K; reused as P [r][c]
    float* Vs  = smx + 2*64*68;   // [64][68]  c-major V

    const int qt = blockIdx.x, h = blockIdx.y, b = blockIdx.z;
    const int tid = threadIdx.x;
    const int ty = tid >> 4, tx = tid & 15;
    const int rowQ0 = b*TS + qt*64;
    const int rowK0 = b*TS;

    // Load Q tile, transpose to kk-major, pre-scale by 1/sqrt(64).
    #pragma unroll
    for (int p = 0; p < 4; ++p) {
        int lin = p*1024 + tid*4;
        int r = lin >> 6, d = lin & 63;
        float4 q = *(const float4*)&Q[(rowQ0+r)*DM + h*HD + d];
        Qt[(d+0)*68 + r] = q.x * 0.125f;
        Qt[(d+1)*68 + r] = q.y * 0.125f;
        Qt[(d+2)*68 + r] = q.z * 0.125f;
        Qt[(d+3)*68 + r] = q.w * 0.125f;
    }

    u64 acc2[8];
    #pragma unroll
    for (int i = 0; i < 8; ++i) acc2[i] = 0ull;
    float mprev[4], lsum[4];
    #pragma unroll
    for (int i = 0; i < 4; ++i) { mprev[i] = -1e30f; lsum[i] = 0.f; }

    for (int kt = 0; kt <= qt; ++kt) {
        __syncthreads();   // prev iter done with KtP/Vs (and Qt visible, iter 0)
        #pragma unroll
        for (int p = 0; p < 4; ++p) {
            int lin = p*1024 + tid*4;
            int a = lin >> 6, e = lin & 63;
            *(float4*)&KtP[a*68 + e] = *(const float4*)&Kt[a*BT + rowK0 + kt*64 + e];
            *(float4*)&Vs [a*68 + e] = *(const float4*)&V[(rowK0 + kt*64 + a)*HD + e];
        }
        __syncthreads();

        // S = Qs @ K^T : 8 fma2 + 2 LDS.128 + 4 dup per kk
        u64 s2[8];
        #pragma unroll
        for (int i = 0; i < 8; ++i) s2[i] = 0ull;
        #pragma unroll 16
        for (int kk = 0; kk < 64; ++kk) {
            float4 q4 = *(const float4*)&Qt[kk*68 + ty*4];
            ulonglong2 k2 = *(const ulonglong2*)&KtP[kk*68 + tx*4];
            u64 a0 = dup2(q4.x), a1 = dup2(q4.y), a2 = dup2(q4.z), a3 = dup2(q4.w);
            fma2(s2[0],a0,k2.x); fma2(s2[1],a0,k2.y);
            fma2(s2[2],a1,k2.x); fma2(s2[3],a1,k2.y);
            fma2(s2[4],a2,k2.x); fma2(s2[5],a2,k2.y);
            fma2(s2[6],a3,k2.x); fma2(s2[7],a3,k2.y);
        }

        float s[16];
        #pragma unroll
        for (int i = 0; i < 4; ++i) {
            float2 a = unpk(s2[i*2]), c = unpk(s2[i*2+1]);
            s[i*4+0]=a.x; s[i*4+1]=a.y; s[i*4+2]=c.x; s[i*4+3]=c.y;
        }

        if (kt == qt) {   // causal mask, diagonal tile only
            #pragma unroll
            for (int i = 0; i < 4; ++i)
                #pragma unroll
                for (int j = 0; j < 4; ++j)
                    if (tx*4+j > ty*4+i) s[i*4+j] = -1e30f;
        }

        // Online softmax (rows live in 16-lane shfl groups)
        #pragma unroll
        for (int i = 0; i < 4; ++i) {
            float mx = fmaxf(fmaxf(s[i*4],s[i*4+1]), fmaxf(s[i*4+2],s[i*4+3]));
            #pragma unroll
            for (int o = 8; o; o >>= 1) mx = fmaxf(mx, __shfl_xor_sync(0xffffffffu, mx, o));
            float mnew = fmaxf(mprev[i], mx);
            float sc   = __expf(mprev[i] - mnew);
            float rs = 0.f;
            #pragma unroll
            for (int j = 0; j < 4; ++j) { s[i*4+j] = __expf(s[i*4+j] - mnew); rs += s[i*4+j]; }
            #pragma unroll
            for (int o = 8; o; o >>= 1) rs += __shfl_xor_sync(0xffffffffu, rs, o);
            lsum[i]  = lsum[i]*sc + rs;
            mprev[i] = mnew;
            u64 sc2 = dup2(sc);
            acc2[i*2]   = mul2(acc2[i*2],   sc2);
            acc2[i*2+1] = mul2(acc2[i*2+1], sc2);
        }

        // Stage P row-major into the K buffer
        __syncthreads();
        #pragma unroll
        for (int i = 0; i < 4; ++i)
            #pragma unroll
            for (int j = 0; j < 4; ++j)
                KtP[(ty*4+i)*68 + tx*4+j] = s[i*4+j];
        __syncthreads();

        // O += P @ V : per c-quad, 8 LDS.128 + 16 dup + 32 fma2
        #pragma unroll 4
        for (int cq = 0; cq < 16; ++cq) {
            float rp[16];
            #pragma unroll
            for (int i = 0; i < 4; ++i)
                *(float4*)&rp[i*4] = *(const float4*)&KtP[(ty*4+i)*68 + cq*4];
            #pragma unroll
            for (int q = 0; q < 4; ++q) {
                ulonglong2 v2 = *(const ulonglong2*)&Vs[(cq*4+q)*68 + tx*4];
                #pragma unroll
                for (int i = 0; i < 4; ++i) {
                    u64 a = dup2(rp[i*4+q]);
                    fma2(acc2[i*2],   a, v2.x);
                    fma2(acc2[i*2+1], a, v2.y);
                }
            }
        }
    }

    // Normalize + write Y (natural layout for the output projection)
    #pragma unroll
    for (int i = 0; i < 4; ++i) {
        float inv = 1.f / lsum[i];
        float2 a = unpk(acc2[i*2]), c = unpk(acc2[i*2+1]);
        float4 o = make_float4(a.x*inv, a.y*inv, c.x*inv, c.y*inv);
        *(float4*)&Y[(rowQ0+ty*4+i)*DM + h*HD + tx*4] = o;
    }
}

// ---------------- launch ----------------
extern "C" void kernel_launch(void* const* d_in, const int* in_sizes, int n_in,
                              void* d_out, int out_size) {
    const float* x  = (const float*)d_in[0];
    const float* Wq = (const float*)d_in[1];
    const float* Wk = (const float*)d_in[2];
    const float* Wv = (const float*)d_in[3];
    const float* Wo = (const float*)d_in[4];
    float* out = (float*)d_out;

    float *Qb, *Ktb, *Vb, *Yb;
    cudaGetSymbolAddress((void**)&Qb,  g_Q);
    cudaGetSymbolAddress((void**)&Ktb, g_Kt);
    cudaGetSymbolAddress((void**)&Vb,  g_V);
    cudaGetSymbolAddress((void**)&Yb,  g_Y);

    const int fsm = 3 * 64 * 68 * (int)sizeof(float);  // 52224 B
    cudaFuncSetAttribute(flash2, cudaFuncAttributeMaxDynamicSharedMemorySize, fsm);

    // Q = x @ Wq                          (4096 x 1024 x 1024)
    sgemm2<128,128,16,16,4,false><<<dim3(DM/128, BT/128), 256>>>(x, Wq, Qb, BT, DM, DM);
    // K^T = (x @ Wk)^T  -> [64][4096]     (transposed store)
    sgemm2<64,64,16,4,4,true>   <<<dim3(1, BT/64), 256>>>(x, Wk, Ktb, BT, HD, DM);
    // V = x @ Wv                          (natural [4096][64])
    sgemm2<64,64,16,4,4,false>  <<<dim3(1, BT/64), 256>>>(x, Wv, Vb, BT, HD, DM);
    // causal MQA attention -> Y
    flash2<<<dim3(TS/64, NH, 2), 256, fsm>>>(Qb, Ktb, Vb, Yb);
    // out = Y @ Wo                        (4096 x 1024 x 1024)
    sgemm2<128,128,16,16,4,false><<<dim3(DM/128, BT/128), 256>>>(Yb, Wo, out, BT, DM, DM);
}